// round 4
// baseline (speedup 1.0000x reference)
#include <cuda_runtime.h>
#include <cstdint>

// CRF negative log-likelihood, B=256, T=2048, D=64.
// Inputs (metadata order): p [B,T,D] f32, y [B,T,D] i32 (one-hot), mask [B,T] i32,
// transition [D,D] f32. Output: [B] f32.
//
// Linear-space forward algorithm with periodic renormalization:
//   u_t[j] = exp(p_t[j]) * sum_i u_{t-1}[i] * exp(T[i][j])
//   renormalize by S = sum_j u (every 8 steps), logZ accumulates log(S).
// One CTA per batch, 128 threads: warp w owns states j in [16w,16w+16),
// lane half h splits the i-sum (32 FMAs/thread/step), combined via shfl.xor 16.
// expT column halves live in registers (32 per thread). One __syncthreads per step
// (double-buffered shared u + per-warp partials). s1 (emission), s2 (transition
// bigram score, via per-step integer label redux) and length L fused in.

#define TT 2048
#define DD 64
#define RN 8   // renormalization period (worst-case growth 8*6.1 < ln(FLT_MAX))

__device__ __forceinline__ int redux_add_s32(int v) {
    int r;
    asm volatile("redux.sync.add.s32 %0, %1, 0xffffffff;" : "=r"(r) : "r"(v));
    return r;
}

__global__ __launch_bounds__(128, 8)
void crf_fwd_kernel(const float* __restrict__ p,
                    const int*   __restrict__ y,
                    const int*   __restrict__ mask,
                    const float* __restrict__ trans,
                    float*       __restrict__ out)
{
    const int b   = blockIdx.x;
    const int tid = threadIdx.x;
    const int w   = tid >> 5;          // warp id 0..3
    const int l   = tid & 31;          // lane
    const int j   = (w << 4) | (l & 15);  // my state 0..63
    const int h   = l >> 4;            // i-half 0/1

    __shared__ float ubuf[2][DD];      // double-buffered forward vector
    __shared__ float pv[2][4];         // per-warp partial sums of u (renorm steps)
    __shared__ int   plab[2][4];       // per-warp partial label sums
    __shared__ float sred[4];
    __shared__ int   ired[4];

    // ---- length L = T - sum(mask[b,:]) ----
    int msum = 0;
    const int* maskb = mask + (size_t)b * TT;
    for (int i = tid; i < TT; i += 128) msum += maskb[i];
    #pragma unroll
    for (int s = 16; s >= 1; s >>= 1) msum += __shfl_xor_sync(0xffffffffu, msum, s);
    if (l == 0) ired[w] = msum;
    __syncthreads();
    const int L = TT - (ired[0] + ired[1] + ired[2] + ired[3]);

    // ---- expT half-column in registers: col[k] = exp(trans[(h*32+k)][j]) ----
    float col[32];
    #pragma unroll
    for (int k = 0; k < 32; k++)
        col[k] = __expf(trans[(h * 32 + k) * DD + j]);

    const float* pb = p + (size_t)b * TT * DD;
    const int*   yb = y + (size_t)b * TT * DD;

    float s1 = 0.f, s2 = 0.f, logz = 0.f;
    int labPrev = 0;

    // ---- t = 0 prologue ----
    float pj = 0.f; int yj = 0;
    if (h == 0) { pj = pb[j]; yj = yb[j]; }
    {
        float w0 = 0.f;
        if (h == 0) {
            w0 = __expf(pj);
            if (yj) s1 += pj;
            ubuf[0][j] = w0;
        }
        int lc = (h == 0 && yj) ? j : 0;
        lc = redux_add_s32(lc);
        if (l == 0) plab[0][w] = lc;
        float vv = w0;                       // h1 lanes contribute 0
        #pragma unroll
        for (int s = 8; s >= 1; s >>= 1) vv += __shfl_xor_sync(0xffffffffu, vv, s);
        if (l == 0) pv[0][w] = vv;
    }
    // prefetch t = 1
    if (L > 1 && h == 0) { pj = pb[DD + j]; yj = yb[DD + j]; }
    __syncthreads();

    // ---- main recursion t = 1 .. L-1 ----
    for (int t = 1; t < L; t++) {
        const int wb = t & 1, rb = wb ^ 1;

        // label from step t-1 (partials visible after previous barrier)
        int labNew = plab[rb][0] + plab[rb][1] + plab[rb][2] + plab[rb][3];
        if (t >= 2) s2 += trans[labPrev * DD + labNew];
        labPrev = labNew;

        // renorm application (S computed at step t-1)
        float rinv = 1.f;
        if (((t - 1) & (RN - 1)) == 0) {
            float S = pv[rb][0] + pv[rb][1] + pv[rb][2] + pv[rb][3];
            rinv = __fdividef(1.f, S);
            logz += __logf(S);
        }

        float ex = __expf(pj);   // exp(p_t[j]) (valid on h0 lanes)

        // mat-vec over my i-half: 8 x LDS.128 (broadcast) + 32 FMAs
        const float4* ub = reinterpret_cast<const float4*>(&ubuf[rb][h * 32]);
        float a0 = 0.f, a1 = 0.f, a2 = 0.f, a3 = 0.f;
        #pragma unroll
        for (int k = 0; k < 8; k++) {
            float4 q = ub[k];
            a0 = fmaf(q.x, col[4 * k + 0], a0);
            a1 = fmaf(q.y, col[4 * k + 1], a1);
            a2 = fmaf(q.z, col[4 * k + 2], a2);
            a3 = fmaf(q.w, col[4 * k + 3], a3);
        }
        float acc = (a0 + a1) + (a2 + a3);
        acc += __shfl_xor_sync(0xffffffffu, acc, 16);  // combine i-halves

        const float pcur = pj;
        const int   ycur = yj;
        // prefetch step t+1
        if (t + 1 < L && h == 0) {
            pj = pb[(size_t)(t + 1) * DD + j];
            yj = yb[(size_t)(t + 1) * DD + j];
        }

        float v = 0.f;
        if (h == 0) {
            v = ex * acc * rinv;
            if (ycur) s1 += pcur;
            ubuf[wb][j] = v;
        }
        int lc = (h == 0 && ycur) ? j : 0;
        lc = redux_add_s32(lc);
        if (l == 0) plab[wb][w] = lc;

        const bool doSum = ((t & (RN - 1)) == 0) || (t == L - 1);
        if (doSum) {
            float vv = v;                    // h1 lanes contribute 0
            #pragma unroll
            for (int s = 8; s >= 1; s >>= 1) vv += __shfl_xor_sync(0xffffffffu, vv, s);
            if (l == 0) pv[wb][w] = vv;
        }
        __syncthreads();
    }

    // ---- epilogue ----
    const int fb = (L - 1) & 1;
    {
        int labNew = plab[fb][0] + plab[fb][1] + plab[fb][2] + plab[fb][3];
        if (L >= 2) s2 += trans[labPrev * DD + labNew];   // final pair (L-2, L-1)
    }
    {
        float S = pv[fb][0] + pv[fb][1] + pv[fb][2] + pv[fb][3];
        logz += __logf(S);
    }

    // block-reduce s1 (held on h0 lanes only)
    float s1w = s1;
    #pragma unroll
    for (int s = 16; s >= 1; s >>= 1) s1w += __shfl_xor_sync(0xffffffffu, s1w, s);
    if (l == 0) sred[w] = s1w;
    __syncthreads();
    if (tid == 0) {
        float s1t = sred[0] + sred[1] + sred[2] + sred[3];
        out[b] = logz - s1t - s2;
    }
}

extern "C" void kernel_launch(void* const* d_in, const int* in_sizes, int n_in,
                              void* d_out, int out_size) {
    const float* p     = (const float*)d_in[0];
    const int*   y     = (const int*)d_in[1];
    const int*   mask  = (const int*)d_in[2];
    const float* trans = (const float*)d_in[3];
    float* out = (float*)d_out;
    (void)in_sizes; (void)n_in; (void)out_size;
    crf_fwd_kernel<<<256, 128>>>(p, y, mask, trans, out);
}

// round 5
// speedup vs baseline: 4.7610x; 4.7610x over previous
#include <cuda_runtime.h>
#include <cstdint>

// CRF negative log-likelihood, B=256, T=2048, D=64.
// Two-kernel split:
//   crf_score_kernel (parallel): per-batch length L, emission score s1,
//     transition score s2 -> g_len / g_s12 scratch.
//   crf_fwd2 (serial chain): linear-space forward recursion with RN=8
//     renormalization, 8-step unrolled blocks, 8-deep register prefetch of p,
//     exps hoisted to block start. One CTA per batch, 128 threads:
//     warp w owns states 16w..16w+15, lane-half h splits the i-sum,
//     combined via shfl.xor 16. expT half-columns in registers.

#define TT 2048
#define DD 64

__device__ float g_s12[256];
__device__ int   g_len[256];

// ---------------------------------------------------------------------------
// Kernel 1: L, s1 (emission), s2 (transition bigram) — fully parallel
// ---------------------------------------------------------------------------
__global__ __launch_bounds__(256)
void crf_score_kernel(const float* __restrict__ p,
                      const int*   __restrict__ y,
                      const int*   __restrict__ mask,
                      const float* __restrict__ trans)
{
    const int b   = blockIdx.x;
    const int tid = threadIdx.x;

    __shared__ short lab[TT];
    __shared__ float fred[8];
    __shared__ int   ired[8];

    // length: L = T - sum(mask)
    int msum = 0;
    const int* mb = mask + (size_t)b * TT;
    for (int t = tid; t < TT; t += 256) msum += mb[t];
    #pragma unroll
    for (int s = 16; s >= 1; s >>= 1) msum += __shfl_xor_sync(0xffffffffu, msum, s);
    if ((tid & 31) == 0) ired[tid >> 5] = msum;

    // labels from one-hot via int4 dot with index vector
    const int4* yb = reinterpret_cast<const int4*>(y + (size_t)b * TT * DD);
    for (int t = tid; t < TT; t += 256) {
        const int4* row = yb + t * 16;
        int labv = 0;
        #pragma unroll
        for (int k = 0; k < 16; k++) {
            int4 v = row[k];
            labv += v.x * (4 * k) + v.y * (4 * k + 1) + v.z * (4 * k + 2) + v.w * (4 * k + 3);
        }
        lab[t] = (short)labv;
    }
    __syncthreads();

    const int L = TT - (ired[0] + ired[1] + ired[2] + ired[3] +
                        ired[4] + ired[5] + ired[6] + ired[7]);
    if (tid == 0) g_len[b] = L;

    const float* pb = p + (size_t)b * TT * DD;
    float s = 0.f;
    for (int t = tid; t < L; t += 256) {
        int lt = lab[t];
        s += pb[(size_t)t * DD + lt];
        if (t < L - 1) s += trans[lt * DD + lab[t + 1]];
    }
    #pragma unroll
    for (int ss = 16; ss >= 1; ss >>= 1) s += __shfl_xor_sync(0xffffffffu, s, ss);
    if ((tid & 31) == 0) fred[tid >> 5] = s;
    __syncthreads();
    if (tid == 0) {
        float tot = 0.f;
        #pragma unroll
        for (int k = 0; k < 8; k++) tot += fred[k];
        g_s12[b] = tot;
    }
}

// ---------------------------------------------------------------------------
// Kernel 2: serial forward recursion (u-chain only)
// ---------------------------------------------------------------------------
__global__ __launch_bounds__(128, 4)
void crf_fwd2(const float* __restrict__ p,
              const float* __restrict__ trans,
              float*       __restrict__ out)
{
    const int b   = blockIdx.x;
    const int tid = threadIdx.x;
    const int w   = tid >> 5;
    const int l   = tid & 31;
    const int j   = (w << 4) | (l & 15);   // my state
    const int h   = l >> 4;                // i-half

    __shared__ float ubuf[2][DD];
    __shared__ float pv[4];

    // expT half-column in registers
    float col[32];
    #pragma unroll
    for (int k = 0; k < 32; k++)
        col[k] = __expf(trans[(h * 32 + k) * DD + j]);

    const int L = g_len[b];
    const float* pb = p + (size_t)b * TT * DD;

    float logz = 0.f;

    // t = 0 prologue: u0 = exp(p0), first partial sum
    {
        float w0 = 0.f;
        if (h == 0) { w0 = __expf(pb[j]); ubuf[0][j] = w0; }
        float vv = w0;
        #pragma unroll
        for (int s = 8; s >= 1; s >>= 1) vv += __shfl_xor_sync(0xffffffffu, vv, s);
        if (l == 0) pv[w] = vv;
    }

    // preload block t = 1..8
    float pf[8], exs[8];
    int base = 1;
    if (h == 0) {
        #pragma unroll
        for (int k = 0; k < 8; k++)
            pf[k] = (base + k < L) ? pb[(size_t)(base + k) * DD + j] : 0.f;
    }
    __syncthreads();

    float rinv = 1.f;

    // ---- main blocks of 8 steps (base ≡ 1 mod 8) ----
    while (base + 7 <= L - 1) {
        // hoist exps off the critical path, then burst-prefetch next block
        #pragma unroll
        for (int k = 0; k < 8; k++) exs[k] = __expf(pf[k]);
        if (h == 0 && base + 8 <= L - 1) {
            #pragma unroll
            for (int k = 0; k < 8; k++) {
                int t2 = base + 8 + k;
                pf[k] = (t2 < L) ? pb[(size_t)t2 * DD + j] : 0.f;
            }
        }
        // renorm from previous block's sum (t-1 = base-1 ≡ 0 mod 8)
        {
            float S = pv[0] + pv[1] + pv[2] + pv[3];
            rinv = __fdividef(1.f, S);
            logz += __logf(S);
        }

        #pragma unroll
        for (int k = 0; k < 8; k++) {
            const int t  = base + k;
            const int wb = t & 1, rb = wb ^ 1;

            const float4* ub = reinterpret_cast<const float4*>(&ubuf[rb][h * 32]);
            float a0 = 0.f, a1 = 0.f, a2 = 0.f, a3 = 0.f;
            #pragma unroll
            for (int q = 0; q < 8; q++) {
                float4 v4 = ub[q];
                a0 = fmaf(v4.x, col[4 * q + 0], a0);
                a1 = fmaf(v4.y, col[4 * q + 1], a1);
                a2 = fmaf(v4.z, col[4 * q + 2], a2);
                a3 = fmaf(v4.w, col[4 * q + 3], a3);
            }
            float acc = (a0 + a1) + (a2 + a3);
            acc += __shfl_xor_sync(0xffffffffu, acc, 16);

            float v = 0.f;
            if (h == 0) {
                v = exs[k] * acc;
                if (k == 0) v *= rinv;
                ubuf[wb][j] = v;
            }
            if (k == 7) {   // sum for next renorm / final logZ
                float vv = v;
                #pragma unroll
                for (int s = 8; s >= 1; s >>= 1) vv += __shfl_xor_sync(0xffffffffu, vv, s);
                if (l == 0) pv[w] = vv;
            }
            __syncthreads();
        }
        base += 8;
    }

    // ---- remainder: t = base .. L-1 (fewer than 8 steps) ----
    for (int t = base; t <= L - 1; t++) {
        if (t == base) {   // apply renorm once (base-1 ≡ 0 mod 8)
            float S = pv[0] + pv[1] + pv[2] + pv[3];
            rinv = __fdividef(1.f, S);
            logz += __logf(S);
        }
        const int wb = t & 1, rb = wb ^ 1;
        float ex = 0.f;
        if (h == 0) ex = __expf(pb[(size_t)t * DD + j]);

        const float4* ub = reinterpret_cast<const float4*>(&ubuf[rb][h * 32]);
        float a0 = 0.f, a1 = 0.f, a2 = 0.f, a3 = 0.f;
        #pragma unroll
        for (int q = 0; q < 8; q++) {
            float4 v4 = ub[q];
            a0 = fmaf(v4.x, col[4 * q + 0], a0);
            a1 = fmaf(v4.y, col[4 * q + 1], a1);
            a2 = fmaf(v4.z, col[4 * q + 2], a2);
            a3 = fmaf(v4.w, col[4 * q + 3], a3);
        }
        float acc = (a0 + a1) + (a2 + a3);
        acc += __shfl_xor_sync(0xffffffffu, acc, 16);

        float v = 0.f;
        if (h == 0) {
            v = ex * acc;
            if (t == base) v *= rinv;
            ubuf[wb][j] = v;
        }
        if (t == L - 1) {
            float vv = v;
            #pragma unroll
            for (int s = 8; s >= 1; s >>= 1) vv += __shfl_xor_sync(0xffffffffu, vv, s);
            if (l == 0) pv[w] = vv;
        }
        __syncthreads();
    }

    // ---- epilogue ----
    if (tid == 0) {
        float S = pv[0] + pv[1] + pv[2] + pv[3];
        logz += __logf(S);
        out[b] = logz - g_s12[b];
    }
}

extern "C" void kernel_launch(void* const* d_in, const int* in_sizes, int n_in,
                              void* d_out, int out_size) {
    const float* p     = (const float*)d_in[0];
    const int*   y     = (const int*)d_in[1];
    const int*   mask  = (const int*)d_in[2];
    const float* trans = (const float*)d_in[3];
    float* out = (float*)d_out;
    (void)in_sizes; (void)n_in; (void)out_size;
    crf_score_kernel<<<256, 256>>>(p, y, mask, trans);
    crf_fwd2<<<256, 128>>>(p, trans, out);
}